// round 8
// baseline (speedup 1.0000x reference)
#include <cuda_runtime.h>
#include <cuda_fp16.h>
#include <cstdint>

// Problem constants (fixed shapes per reference setup_inputs)
#define BATCH    32
#define CH       64
#define HW       4096          // 64*64
#define NPIX     131072        // BATCH*HW
#define NCODE    1024
#define PPC      128           // pixels per CTA (= GEMM M)
#define BROWS    64            // codes per chunk (= GEMM N)
#define NCHK     (NCODE / BROWS)  // 16
#define KDIM     64            // fp16 hi-only GEMM K
#define KSTEPS   (KDIM / 16)   // 4
#define ASTRIDE  72            // fp16 elems per row (144B: 144%128=16 -> ldsm conflict-free)
#define BSTRIDE  72
#define MARGIN   0.04f         // fp16-hi error ~3.4e-3 std -> 12 sigma
#define FIX_CAP  32768
#define FIX_WARPS (512 * 8)    // fixup grid: 512 blocks x 8 warps

#define XQ_ELEMS  (NPIX * CH)  // 8388608
#define IDX_ELEMS NPIX         // 131072

#define A_BYTES   (PPC * ASTRIDE * 2)    // 18432
#define B_BYTES   (BROWS * BSTRIDE * 2)  // 9216
#define DYN_SMEM  (A_BYTES + 2 * B_BYTES)  // 36864

// Scratch (device globals — no allocation allowed)
__device__ float              g_e2[NCODE];
__device__ int                g_counts[NCODE];
__device__ unsigned long long g_loss_sum;
__device__ int                g_fix_cnt;
__device__ int                g_fix_list[FIX_CAP];
__device__ __half             g_Bpack[NCODE * BSTRIDE];   // [code][k] fp16 hi, padded

// ---------------------------------------------------------------------------
// SM80+-vintage PTX helpers (all supported on base sm_100)
// ---------------------------------------------------------------------------
__device__ __forceinline__ uint32_t smem_u32(const void* p) {
    uint32_t a;
    asm("{ .reg .u64 t; cvta.to.shared.u64 t, %1; cvt.u32.u64 %0, t; }"
        : "=r"(a) : "l"(p));
    return a;
}
__device__ __forceinline__ void ldsm_x4(uint32_t* r, uint32_t addr) {
    asm volatile("ldmatrix.sync.aligned.m8n8.x4.shared.b16 {%0,%1,%2,%3}, [%4];"
                 : "=r"(r[0]), "=r"(r[1]), "=r"(r[2]), "=r"(r[3]) : "r"(addr));
}
__device__ __forceinline__ void ldsm_x2(uint32_t* r, uint32_t addr) {
    asm volatile("ldmatrix.sync.aligned.m8n8.x2.shared.b16 {%0,%1}, [%2];"
                 : "=r"(r[0]), "=r"(r[1]) : "r"(addr));
}
__device__ __forceinline__ void mma_f16(float* d, const uint32_t* a, const uint32_t* b) {
    asm volatile(
        "mma.sync.aligned.m16n8k16.row.col.f32.f16.f16.f32 "
        "{%0,%1,%2,%3}, {%4,%5,%6,%7}, {%8,%9}, {%0,%1,%2,%3};"
        : "+f"(d[0]), "+f"(d[1]), "+f"(d[2]), "+f"(d[3])
        : "r"(a[0]), "r"(a[1]), "r"(a[2]), "r"(a[3]), "r"(b[0]), "r"(b[1]));
}
#define CP_ASYNC16(dst, src) \
    asm volatile("cp.async.cg.shared.global [%0], [%1], 16;" :: "r"(dst), "l"(src))
#define CP_COMMIT() asm volatile("cp.async.commit_group;" ::: "memory")
#define CP_WAIT1()  asm volatile("cp.async.wait_group 1;" ::: "memory")
#define CP_WAIT0()  asm volatile("cp.async.wait_group 0;" ::: "memory")

// ---------------------------------------------------------------------------
// Prep A: ||e||^2 per code, zero accumulators
// ---------------------------------------------------------------------------
__global__ void vq_prep(const float* __restrict__ emb) {
    int c = blockIdx.x * blockDim.x + threadIdx.x;
    if (c < NCODE) {
        const float* row = emb + c * CH;
        float s = 0.f;
        #pragma unroll
        for (int k = 0; k < CH; k++) s = fmaf(row[k], row[k], s);
        g_e2[c]     = s;
        g_counts[c] = 0;
    }
    if (c == 0) { g_loss_sum = 0ull; g_fix_cnt = 0; }
}

// ---------------------------------------------------------------------------
// Prep B: pack codebook as [code][k] fp16 hi (stride 72, pad zeroed)
// ---------------------------------------------------------------------------
__global__ void vq_pack(const float* __restrict__ emb) {
    int c = blockIdx.x * blockDim.x + threadIdx.x;
    if (c >= NCODE) return;
    __half* dst = g_Bpack + c * BSTRIDE;
    #pragma unroll
    for (int k = 0; k < CH; k++) dst[k] = __float2half_rn(emb[c * CH + k]);
    #pragma unroll
    for (int k = CH; k < BSTRIDE; k++) dst[k] = __ushort_as_half(0);
}

// ---------------------------------------------------------------------------
// Main: fp16 HMMA distance GEMM (hi-only), argmin fused on accumulators.
//   8 warps: warp_m = wid&3 (32 pixels), warp_n = wid>>2 (32 codes of chunk)
// ---------------------------------------------------------------------------
extern __shared__ char smem_dyn[];   // A[128][72] fp16 | B0 | B1

__global__ __launch_bounds__(256, 2) void vq_main(
        const float* __restrict__ x_in,
        const float* __restrict__ emb,
        float* __restrict__ out_xq,
        float* __restrict__ out_idx)
{
    __shared__ float e2s[NCODE];
    __shared__ float x2s[PPC];
    __shared__ int   ridx[PPC];
    __shared__ float sm_v1[PPC][2], sm_v2[PPC][2];
    __shared__ int   sm_ix[PPC][2];
    __shared__ unsigned long long s_loss;

    __half* As = (__half*)smem_dyn;
    const uint32_t As_u = smem_u32(smem_dyn);
    const uint32_t Bu[2] = { As_u + A_BYTES, As_u + A_BYTES + B_BYTES };

    const int t      = threadIdx.x;
    const int lane   = t & 31;
    const int wid    = t >> 5;
    const int warp_m = wid & 3;
    const int warp_n = wid >> 2;
    const int b      = blockIdx.x >> 5;
    const int hw     = (blockIdx.x & 31) * PPC;
    const int pbase  = blockIdx.x * PPC;

    if (t == 0) s_loss = 0ull;
    if (t < PPC) x2s[t] = 0.f;
    #pragma unroll
    for (int i = 0; i < 4; i++) e2s[i * 256 + t] = g_e2[i * 256 + t];
    __syncthreads();

    // ---- prefetch B chunk 0 (64 rows x 9 x 16B segs = 576) ----
    {
        #pragma unroll
        for (int i = 0; i < 3; i++) {
            int seg = i * 256 + t;
            if (seg < 576) {
                int row = seg / 9, off = seg % 9;
                CP_ASYNC16(Bu[0] + row * (BSTRIDE * 2) + off * 16,
                           (const char*)(g_Bpack + row * BSTRIDE) + off * 16);
            }
        }
        CP_COMMIT();
    }

    // ---- A tile: gmem [c][p] fp32 -> smem [p][k] fp16 hi + x2 ----
    #pragma unroll
    for (int r = 0; r < 8; r++) {
        int e  = r * 256 + t;
        int c  = e >> 5;
        int p4 = (e & 31) * 4;
        float4 v = *(const float4*)(x_in + (b * CH + c) * HW + hw + p4);
        float xv[4] = {v.x, v.y, v.z, v.w};
        #pragma unroll
        for (int q = 0; q < 4; q++) {
            int p = p4 + q;
            float x = xv[q];
            As[p * ASTRIDE + c] = __float2half_rn(x);
            atomicAdd(&x2s[p], x * x);
        }
    }
    __syncthreads();

    // ldmatrix base addresses (bytes); row stride 144B (144%128=16 -> conflict-free)
    uint32_t a_base[2];
    #pragma unroll
    for (int i = 0; i < 2; i++)
        a_base[i] = As_u + (warp_m * 32 + i * 16 + (lane & 15)) * (ASTRIDE * 2)
                  + (lane >> 4) * 16;
    const uint32_t b_row_off = (warp_n * 32 + (lane & 7)) * (BSTRIDE * 2)
                             + ((lane >> 3) & 1) * 16;

    float minv[4], min2[4];
    int   mini[4];
    #pragma unroll
    for (int s = 0; s < 4; s++) { minv[s] = 3.4e38f; min2[s] = 3.4e38f; mini[s] = 0; }

    for (int chunk = 0; chunk < NCHK; chunk++) {
        const int buf = chunk & 1;
        if (chunk + 1 < NCHK) {
            #pragma unroll
            for (int i = 0; i < 3; i++) {
                int seg = i * 256 + t;
                if (seg < 576) {
                    int row = seg / 9, off = seg % 9;
                    CP_ASYNC16(Bu[buf ^ 1] + row * (BSTRIDE * 2) + off * 16,
                               (const char*)(g_Bpack + ((chunk + 1) * BROWS + row) * BSTRIDE) + off * 16);
                }
            }
            CP_COMMIT();
            CP_WAIT1();
        } else {
            CP_WAIT0();
        }
        __syncthreads();

        // ---- GEMM: 32x32 per warp, K=64 ----
        float acc[2][4][4];
        #pragma unroll
        for (int i = 0; i < 2; i++)
            #pragma unroll
            for (int j = 0; j < 4; j++)
                #pragma unroll
                for (int r = 0; r < 4; r++) acc[i][j][r] = 0.f;

        #pragma unroll
        for (int kk = 0; kk < KSTEPS; kk++) {
            uint32_t af[2][4], bf[4][2];
            #pragma unroll
            for (int i = 0; i < 2; i++) ldsm_x4(af[i], a_base[i] + kk * 32);
            #pragma unroll
            for (int j = 0; j < 4; j++)
                ldsm_x2(bf[j], Bu[buf] + b_row_off + j * 8 * (BSTRIDE * 2) + kk * 32);
            #pragma unroll
            for (int i = 0; i < 2; i++)
                #pragma unroll
                for (int j = 0; j < 4; j++)
                    mma_f16(acc[i][j], af[i], bf[j]);
        }

        // ---- fused epilogue: score + top-2 on fragments ----
        #pragma unroll
        for (int j = 0; j < 4; j++) {
            const int cb = chunk * BROWS + warp_n * 32 + j * 8 + (lane & 3) * 2;
            const float e20 = e2s[cb], e21 = e2s[cb + 1];
            #pragma unroll
            for (int i = 0; i < 2; i++) {
                #pragma unroll
                for (int h = 0; h < 2; h++) {
                    const int sl = i * 2 + h;
                    float s0 = fmaf(-2.f, acc[i][j][h * 2], e20);
                    float s1 = fmaf(-2.f, acc[i][j][h * 2 + 1], e21);
                    if (s0 < minv[sl]) { min2[sl] = minv[sl]; minv[sl] = s0; mini[sl] = cb; }
                    else if (s0 < min2[sl]) min2[sl] = s0;
                    if (s1 < minv[sl]) { min2[sl] = minv[sl]; minv[sl] = s1; mini[sl] = cb + 1; }
                    else if (s1 < min2[sl]) min2[sl] = s1;
                }
            }
        }
        __syncthreads();
    }

    // ---- reduce across the 4 lanes of each row group (xor 1, xor 2) ----
    #pragma unroll
    for (int off = 1; off <= 2; off <<= 1) {
        #pragma unroll
        for (int s = 0; s < 4; s++) {
            float ov = __shfl_xor_sync(0xffffffffu, minv[s], off);
            int   oi = __shfl_xor_sync(0xffffffffu, mini[s], off);
            float o2 = __shfl_xor_sync(0xffffffffu, min2[s], off);
            float hi = fmaxf(minv[s], ov);
            min2[s] = fminf(fminf(min2[s], o2), hi);
            if (ov < minv[s] || (ov == minv[s] && oi < mini[s])) {
                minv[s] = ov; mini[s] = oi;
            }
        }
    }
    if ((lane & 3) == 0) {
        #pragma unroll
        for (int s = 0; s < 4; s++) {
            int p = warp_m * 32 + (s >> 1) * 16 + (lane >> 2) + (s & 1) * 8;
            sm_v1[p][warp_n] = minv[s];
            sm_v2[p][warp_n] = min2[s];
            sm_ix[p][warp_n] = mini[s];
        }
    }
    __syncthreads();

    // ---- per-pixel combine of the two N-halves + outputs ----
    if (t < PPC) {
        float v1 = sm_v1[t][0], v2 = sm_v2[t][0];
        int   ix = sm_ix[t][0];
        float w1 = sm_v1[t][1], w2 = sm_v2[t][1];
        int   wx = sm_ix[t][1];
        float hi = fmaxf(v1, w1);
        float m2 = fminf(fminf(v2, w2), hi);
        if (w1 < v1 || (w1 == v1 && wx < ix)) { v1 = w1; ix = wx; }

        ridx[t] = ix;
        out_idx[pbase + t] = (float)ix;
        atomicAdd(&g_counts[ix], 1);
        if (m2 - v1 < MARGIN) {
            int slot = atomicAdd(&g_fix_cnt, 1);
            if (slot < FIX_CAP) g_fix_list[slot] = pbase + t;
        }
        long long q = llrint((double)(v1 + x2s[t]) * 1048576.0);
        atomicAdd(&s_loss, (unsigned long long)q);
    }
    __syncthreads();
    if (t == 0) atomicAdd(&g_loss_sum, s_loss);

    // ---- quantized output, channel-first, coalesced over pixels ----
    #pragma unroll
    for (int r = 0; r < 32; r++) {
        int e = r * 256 + t;
        int c = e >> 7;
        int p = e & 127;
        out_xq[(b * CH + c) * HW + hw + p] = emb[ridx[p] * CH + c];
    }
}

// ---------------------------------------------------------------------------
// Fixup v2: warp-per-token exact (fp64) argmin, ILP-4 accumulators.
//   Each lane owns codes [lane*32, lane*32+32); shfl tree combine.
// ---------------------------------------------------------------------------
__global__ __launch_bounds__(256) void vq_fixup(
        const float* __restrict__ x_in,
        const float* __restrict__ emb,
        float* __restrict__ out_xq,
        float* __restrict__ out_idx)
{
    __shared__ double xw[8][CH];

    const int t    = threadIdx.x;
    const int lane = t & 31;
    const int wid  = t >> 5;
    int nfix = g_fix_cnt;
    if (nfix > FIX_CAP) nfix = FIX_CAP;

    for (int f = blockIdx.x * 8 + wid; f < nfix; f += FIX_WARPS) {
        const int p  = g_fix_list[f];
        const int b  = p >> 12;
        const int hw = p & 4095;

        xw[wid][lane]      = (double)x_in[(b * CH + lane) * HW + hw];
        xw[wid][lane + 32] = (double)x_in[(b * CH + lane + 32) * HW + hw];
        __syncwarp();

        double bm = 1e300; int bi = 0;
        const int cbase = lane * 32;
        #pragma unroll 1
        for (int g = 0; g < 8; g++) {
            const float* e0 = emb + (cbase + g * 4 + 0) * CH;
            const float* e1 = emb + (cbase + g * 4 + 1) * CH;
            const float* e2 = emb + (cbase + g * 4 + 2) * CH;
            const float* e3 = emb + (cbase + g * 4 + 3) * CH;
            double a0 = 0, a1 = 0, a2 = 0, a3 = 0;
            #pragma unroll 8
            for (int k = 0; k < CH; k++) {
                double xv = xw[wid][k];
                double d0 = xv - (double)e0[k]; a0 = fma(d0, d0, a0);
                double d1 = xv - (double)e1[k]; a1 = fma(d1, d1, a1);
                double d2 = xv - (double)e2[k]; a2 = fma(d2, d2, a2);
                double d3 = xv - (double)e3[k]; a3 = fma(d3, d3, a3);
            }
            if (a0 < bm) { bm = a0; bi = cbase + g * 4 + 0; }
            if (a1 < bm) { bm = a1; bi = cbase + g * 4 + 1; }
            if (a2 < bm) { bm = a2; bi = cbase + g * 4 + 2; }
            if (a3 < bm) { bm = a3; bi = cbase + g * 4 + 3; }
        }
        // cross-lane min (codes ascend with lane -> lower-index tie-break)
        #pragma unroll
        for (int off = 16; off >= 1; off >>= 1) {
            double ov = __shfl_xor_sync(0xffffffffu, bm, off);
            int    oi = __shfl_xor_sync(0xffffffffu, bi, off);
            if (ov < bm || (ov == bm && oi < bi)) { bm = ov; bi = oi; }
        }
        const int    newi = __shfl_sync(0xffffffffu, bi, 0);
        const double newd = __shfl_sync(0xffffffffu, bm, 0);
        const int    oldi = (int)out_idx[p];

        if (newi != oldi) {
            // exact fp64 distance at old index (lane-parallel, fixed sum order)
            const float* eo = emb + oldi * CH;
            double d0 = xw[wid][lane]      - (double)eo[lane];
            double d1 = xw[wid][lane + 32] - (double)eo[lane + 32];
            double dl = fma(d0, d0, d1 * d1);
            #pragma unroll
            for (int off = 16; off >= 1; off >>= 1)
                dl += __shfl_xor_sync(0xffffffffu, dl, off);
            if (lane == 0) {
                atomicAdd(&g_counts[oldi], -1);
                atomicAdd(&g_counts[newi],  1);
                long long dq = llrint((newd - dl) * 1048576.0);
                atomicAdd(&g_loss_sum, (unsigned long long)dq);  // signed wrap ok
                out_idx[p] = (float)newi;
            }
            out_xq[(b * CH + lane) * HW + hw]        = emb[newi * CH + lane];
            out_xq[(b * CH + lane + 32) * HW + hw]   = emb[newi * CH + lane + 32];
        }
        __syncwarp();
    }
}

// ---------------------------------------------------------------------------
// Epilogue: vq_loss + perplexity
// ---------------------------------------------------------------------------
__global__ void vq_final(float* __restrict__ out_tail) {
    __shared__ float red[256];
    int t = threadIdx.x;
    float s = 0.f;
    for (int c = t; c < NCODE; c += 256) {
        float p = (float)g_counts[c] * (1.0f / (float)NPIX);
        s += p * logf(p + 1e-10f);
    }
    red[t] = s;
    __syncthreads();
    #pragma unroll
    for (int off = 128; off > 0; off >>= 1) {
        if (t < off) red[t] += red[t + off];
        __syncthreads();
    }
    if (t == 0) {
        double loss_sum = (double)(long long)g_loss_sum / 1048576.0;
        float e_loss = (float)(loss_sum / (double)((long long)NPIX * CH));
        out_tail[0] = 0.25f * e_loss;   // BETA * e_loss
        out_tail[1] = expf(-red[0]);    // perplexity
    }
}

// ---------------------------------------------------------------------------
extern "C" void kernel_launch(void* const* d_in, const int* in_sizes, int n_in,
                              void* d_out, int out_size) {
    const float* x_in = (const float*)d_in[0];
    const float* emb  = (const float*)d_in[1];
    float* out      = (float*)d_out;
    float* out_xq   = out;
    float* out_idx  = out + XQ_ELEMS;
    float* out_tail = out + XQ_ELEMS + IDX_ELEMS;

    cudaFuncSetAttribute(vq_main, cudaFuncAttributeMaxDynamicSharedMemorySize,
                         DYN_SMEM);

    vq_prep <<<(NCODE + 255) / 256, 256>>>(emb);
    vq_pack <<<(NCODE + 255) / 256, 256>>>(emb);
    vq_main <<<NPIX / PPC, 256, DYN_SMEM>>>(x_in, emb, out_xq, out_idx);
    vq_fixup<<<512, 256>>>(x_in, emb, out_xq, out_idx);
    vq_final<<<1, 256>>>(out_tail);
}

// round 9
// speedup vs baseline: 1.2174x; 1.2174x over previous
#include <cuda_runtime.h>
#include <cuda_fp16.h>
#include <cuda_bf16.h>
#include <cstdint>

// Problem constants (fixed shapes per reference setup_inputs)
#define BATCH    32
#define CH       64
#define HW       4096          // 64*64
#define NPIX     131072        // BATCH*HW
#define NCODE    1024
#define PPC      128           // pixels per CTA (= GEMM M)
#define BROWS    64            // codes per chunk (= GEMM N)
#define NCHK     (NCODE / BROWS)  // 16
// ---- tier 1: fp16 hi-only ----
#define KDIM     64
#define KSTEPS   (KDIM / 16)   // 4
#define ASTRIDE  72            // 144B rows: 144%128=16 -> ldsm conflict-free
#define BSTRIDE  72
#define MARGIN1  0.04f         // fp16-hi gap noise ~4.5e-3 std
#define FIX1_CAP 49152
// ---- tier 2: bf16 3-term (R6-proven) ----
#define RKP      192           // A=[hi|hi|lo] x B=[hi|lo|hi]
#define RKSTEPS  (RKP / 16)    // 12
#define RASTRIDE 200           // 400B rows: 400%128=16 -> conflict-free
#define RBSTRIDE 200
#define MARGIN2  1e-3f         // bf16-3term noise ~3e-5 std
#define FIX2_CAP 8192
#define FIX2_WARPS (128 * 8)

#define XQ_ELEMS  (NPIX * CH)  // 8388608
#define IDX_ELEMS NPIX         // 131072

#define A_BYTES   (PPC * ASTRIDE * 2)    // 18432
#define B_BYTES   (BROWS * BSTRIDE * 2)  // 9216
#define DYN_SMEM  (A_BYTES + 2 * B_BYTES)  // 36864

#define RA_BYTES  (PPC * RASTRIDE * 2)   // 51200
#define RB_BYTES  (BROWS * RBSTRIDE * 2) // 25600
#define RDYN_SMEM (RA_BYTES + 2 * RB_BYTES)  // 102400

// Scratch (device globals — no allocation allowed)
__device__ float              g_e2[NCODE];
__device__ int                g_counts[NCODE];
__device__ unsigned long long g_loss_sum;
__device__ int                g_fix1_cnt;
__device__ int                g_fix1[FIX1_CAP];
__device__ int                g_fix2_cnt;
__device__ int                g_fix2[FIX2_CAP];
__device__ float              g_scur[NPIX];               // accounted loss value per pixel
__device__ __half             g_Bpack64[NCODE * BSTRIDE]; // [code][k] fp16 hi (pad 0)
__device__ __nv_bfloat16      g_Bpack192[NCODE * RKP];    // [code][k'] bf16 [hi|lo|hi]

// ---------------------------------------------------------------------------
// SM80+-vintage PTX helpers (base sm_100 safe)
// ---------------------------------------------------------------------------
__device__ __forceinline__ uint32_t smem_u32(const void* p) {
    uint32_t a;
    asm("{ .reg .u64 t; cvta.to.shared.u64 t, %1; cvt.u32.u64 %0, t; }"
        : "=r"(a) : "l"(p));
    return a;
}
__device__ __forceinline__ void ldsm_x4(uint32_t* r, uint32_t addr) {
    asm volatile("ldmatrix.sync.aligned.m8n8.x4.shared.b16 {%0,%1,%2,%3}, [%4];"
                 : "=r"(r[0]), "=r"(r[1]), "=r"(r[2]), "=r"(r[3]) : "r"(addr));
}
__device__ __forceinline__ void ldsm_x2(uint32_t* r, uint32_t addr) {
    asm volatile("ldmatrix.sync.aligned.m8n8.x2.shared.b16 {%0,%1}, [%2];"
                 : "=r"(r[0]), "=r"(r[1]) : "r"(addr));
}
__device__ __forceinline__ void mma_f16(float* d, const uint32_t* a, const uint32_t* b) {
    asm volatile(
        "mma.sync.aligned.m16n8k16.row.col.f32.f16.f16.f32 "
        "{%0,%1,%2,%3}, {%4,%5,%6,%7}, {%8,%9}, {%0,%1,%2,%3};"
        : "+f"(d[0]), "+f"(d[1]), "+f"(d[2]), "+f"(d[3])
        : "r"(a[0]), "r"(a[1]), "r"(a[2]), "r"(a[3]), "r"(b[0]), "r"(b[1]));
}
__device__ __forceinline__ void mma_bf16(float* d, const uint32_t* a, const uint32_t* b) {
    asm volatile(
        "mma.sync.aligned.m16n8k16.row.col.f32.bf16.bf16.f32 "
        "{%0,%1,%2,%3}, {%4,%5,%6,%7}, {%8,%9}, {%0,%1,%2,%3};"
        : "+f"(d[0]), "+f"(d[1]), "+f"(d[2]), "+f"(d[3])
        : "r"(a[0]), "r"(a[1]), "r"(a[2]), "r"(a[3]), "r"(b[0]), "r"(b[1]));
}
#define CP_ASYNC16(dst, src) \
    asm volatile("cp.async.cg.shared.global [%0], [%1], 16;" :: "r"(dst), "l"(src))
#define CP_COMMIT() asm volatile("cp.async.commit_group;" ::: "memory")
#define CP_WAIT1()  asm volatile("cp.async.wait_group 1;" ::: "memory")
#define CP_WAIT0()  asm volatile("cp.async.wait_group 0;" ::: "memory")

// ---------------------------------------------------------------------------
// Prep A: ||e||^2 per code, zero accumulators
// ---------------------------------------------------------------------------
__global__ void vq_prep(const float* __restrict__ emb) {
    int c = blockIdx.x * blockDim.x + threadIdx.x;
    if (c < NCODE) {
        const float* row = emb + c * CH;
        float s = 0.f;
        #pragma unroll
        for (int k = 0; k < CH; k++) s = fmaf(row[k], row[k], s);
        g_e2[c]     = s;
        g_counts[c] = 0;
    }
    if (c == 0) { g_loss_sum = 0ull; g_fix1_cnt = 0; g_fix2_cnt = 0; }
}

// ---------------------------------------------------------------------------
// Prep B: pack both codebook images
// ---------------------------------------------------------------------------
__global__ void vq_pack(const float* __restrict__ emb) {
    int c = blockIdx.x * blockDim.x + threadIdx.x;
    if (c >= NCODE) return;
    __half*        d64  = g_Bpack64  + c * BSTRIDE;
    __nv_bfloat16* d192 = g_Bpack192 + c * RKP;
    #pragma unroll
    for (int k = 0; k < CH; k++) {
        float x = emb[c * CH + k];
        d64[k] = __float2half_rn(x);
        __nv_bfloat16 hi = __float2bfloat16_rn(x);
        __nv_bfloat16 lo = __float2bfloat16_rn(x - __bfloat162float(hi));
        d192[k]       = hi;
        d192[64 + k]  = lo;
        d192[128 + k] = hi;
    }
    #pragma unroll
    for (int k = CH; k < BSTRIDE; k++) d64[k] = __ushort_as_half(0);
}

// ---------------------------------------------------------------------------
// Tier 1: fp16 HMMA distance GEMM (hi-only), argmin fused on accumulators.
// ---------------------------------------------------------------------------
extern __shared__ char smem_dyn[];

__global__ __launch_bounds__(256, 2) void vq_main(
        const float* __restrict__ x_in,
        const float* __restrict__ emb,
        float* __restrict__ out_xq,
        float* __restrict__ out_idx)
{
    __shared__ float e2s[NCODE];
    __shared__ float x2s[PPC];
    __shared__ int   ridx[PPC];
    __shared__ float sm_v1[PPC][2], sm_v2[PPC][2];
    __shared__ int   sm_ix[PPC][2];
    __shared__ unsigned long long s_loss;

    __half* As = (__half*)smem_dyn;
    const uint32_t As_u = smem_u32(smem_dyn);
    const uint32_t Bu[2] = { As_u + A_BYTES, As_u + A_BYTES + B_BYTES };

    const int t      = threadIdx.x;
    const int lane   = t & 31;
    const int wid    = t >> 5;
    const int warp_m = wid & 3;
    const int warp_n = wid >> 2;
    const int b      = blockIdx.x >> 5;
    const int hw     = (blockIdx.x & 31) * PPC;
    const int pbase  = blockIdx.x * PPC;

    if (t == 0) s_loss = 0ull;
    if (t < PPC) x2s[t] = 0.f;
    #pragma unroll
    for (int i = 0; i < 4; i++) e2s[i * 256 + t] = g_e2[i * 256 + t];
    __syncthreads();

    {   // prefetch B chunk 0 (64 rows x 9 segs)
        #pragma unroll
        for (int i = 0; i < 3; i++) {
            int seg = i * 256 + t;
            if (seg < 576) {
                int row = seg / 9, off = seg % 9;
                CP_ASYNC16(Bu[0] + row * (BSTRIDE * 2) + off * 16,
                           (const char*)(g_Bpack64 + row * BSTRIDE) + off * 16);
            }
        }
        CP_COMMIT();
    }

    #pragma unroll
    for (int r = 0; r < 8; r++) {
        int e  = r * 256 + t;
        int c  = e >> 5;
        int p4 = (e & 31) * 4;
        float4 v = *(const float4*)(x_in + (b * CH + c) * HW + hw + p4);
        float xv[4] = {v.x, v.y, v.z, v.w};
        #pragma unroll
        for (int q = 0; q < 4; q++) {
            int p = p4 + q;
            float x = xv[q];
            As[p * ASTRIDE + c] = __float2half_rn(x);
            atomicAdd(&x2s[p], x * x);
        }
    }
    __syncthreads();

    uint32_t a_base[2];
    #pragma unroll
    for (int i = 0; i < 2; i++)
        a_base[i] = As_u + (warp_m * 32 + i * 16 + (lane & 15)) * (ASTRIDE * 2)
                  + (lane >> 4) * 16;
    const uint32_t b_row_off = (warp_n * 32 + (lane & 7)) * (BSTRIDE * 2)
                             + ((lane >> 3) & 1) * 16;

    float minv[4], min2[4];
    int   mini[4];
    #pragma unroll
    for (int s = 0; s < 4; s++) { minv[s] = 3.4e38f; min2[s] = 3.4e38f; mini[s] = 0; }

    for (int chunk = 0; chunk < NCHK; chunk++) {
        const int buf = chunk & 1;
        if (chunk + 1 < NCHK) {
            #pragma unroll
            for (int i = 0; i < 3; i++) {
                int seg = i * 256 + t;
                if (seg < 576) {
                    int row = seg / 9, off = seg % 9;
                    CP_ASYNC16(Bu[buf ^ 1] + row * (BSTRIDE * 2) + off * 16,
                               (const char*)(g_Bpack64 + ((chunk + 1) * BROWS + row) * BSTRIDE) + off * 16);
                }
            }
            CP_COMMIT();
            CP_WAIT1();
        } else {
            CP_WAIT0();
        }
        __syncthreads();

        float acc[2][4][4];
        #pragma unroll
        for (int i = 0; i < 2; i++)
            #pragma unroll
            for (int j = 0; j < 4; j++)
                #pragma unroll
                for (int r = 0; r < 4; r++) acc[i][j][r] = 0.f;

        #pragma unroll
        for (int kk = 0; kk < KSTEPS; kk++) {
            uint32_t af[2][4], bf[4][2];
            #pragma unroll
            for (int i = 0; i < 2; i++) ldsm_x4(af[i], a_base[i] + kk * 32);
            #pragma unroll
            for (int j = 0; j < 4; j++)
                ldsm_x2(bf[j], Bu[buf] + b_row_off + j * 8 * (BSTRIDE * 2) + kk * 32);
            #pragma unroll
            for (int i = 0; i < 2; i++)
                #pragma unroll
                for (int j = 0; j < 4; j++)
                    mma_f16(acc[i][j], af[i], bf[j]);
        }

        #pragma unroll
        for (int j = 0; j < 4; j++) {
            const int cb = chunk * BROWS + warp_n * 32 + j * 8 + (lane & 3) * 2;
            const float e20 = e2s[cb], e21 = e2s[cb + 1];
            #pragma unroll
            for (int i = 0; i < 2; i++) {
                #pragma unroll
                for (int h = 0; h < 2; h++) {
                    const int sl = i * 2 + h;
                    float s0 = fmaf(-2.f, acc[i][j][h * 2], e20);
                    float s1 = fmaf(-2.f, acc[i][j][h * 2 + 1], e21);
                    if (s0 < minv[sl]) { min2[sl] = minv[sl]; minv[sl] = s0; mini[sl] = cb; }
                    else if (s0 < min2[sl]) min2[sl] = s0;
                    if (s1 < minv[sl]) { min2[sl] = minv[sl]; minv[sl] = s1; mini[sl] = cb + 1; }
                    else if (s1 < min2[sl]) min2[sl] = s1;
                }
            }
        }
        __syncthreads();
    }

    #pragma unroll
    for (int off = 1; off <= 2; off <<= 1) {
        #pragma unroll
        for (int s = 0; s < 4; s++) {
            float ov = __shfl_xor_sync(0xffffffffu, minv[s], off);
            int   oi = __shfl_xor_sync(0xffffffffu, mini[s], off);
            float o2 = __shfl_xor_sync(0xffffffffu, min2[s], off);
            float hi = fmaxf(minv[s], ov);
            min2[s] = fminf(fminf(min2[s], o2), hi);
            if (ov < minv[s] || (ov == minv[s] && oi < mini[s])) {
                minv[s] = ov; mini[s] = oi;
            }
        }
    }
    if ((lane & 3) == 0) {
        #pragma unroll
        for (int s = 0; s < 4; s++) {
            int p = warp_m * 32 + (s >> 1) * 16 + (lane >> 2) + (s & 1) * 8;
            sm_v1[p][warp_n] = minv[s];
            sm_v2[p][warp_n] = min2[s];
            sm_ix[p][warp_n] = mini[s];
        }
    }
    __syncthreads();

    if (t < PPC) {
        float v1 = sm_v1[t][0], v2 = sm_v2[t][0];
        int   ix = sm_ix[t][0];
        float w1 = sm_v1[t][1], w2 = sm_v2[t][1];
        int   wx = sm_ix[t][1];
        float hi = fmaxf(v1, w1);
        float m2 = fminf(fminf(v2, w2), hi);
        if (w1 < v1 || (w1 == v1 && wx < ix)) { v1 = w1; ix = wx; }

        ridx[t] = ix;
        out_idx[pbase + t] = (float)ix;
        atomicAdd(&g_counts[ix], 1);
        float sc = v1 + x2s[t];
        g_scur[pbase + t] = sc;
        if (m2 - v1 < MARGIN1) {
            int slot = atomicAdd(&g_fix1_cnt, 1);
            if (slot < FIX1_CAP) g_fix1[slot] = pbase + t;
        }
        long long q = llrint((double)sc * 1048576.0);
        atomicAdd(&s_loss, (unsigned long long)q);
    }
    __syncthreads();
    if (t == 0) atomicAdd(&g_loss_sum, s_loss);

    #pragma unroll
    for (int r = 0; r < 32; r++) {
        int e = r * 256 + t;
        int c = e >> 7;
        int p = e & 127;
        out_xq[(b * CH + c) * HW + hw + p] = emb[ridx[p] * CH + c];
    }
}

// ---------------------------------------------------------------------------
// Tier 2: bf16 3-term K=192 GEMM on gathered flagged tokens (R6-proven math)
// ---------------------------------------------------------------------------
__global__ __launch_bounds__(256, 2) void vq_refine(
        const float* __restrict__ x_in,
        const float* __restrict__ emb,
        float* __restrict__ out_xq,
        float* __restrict__ out_idx)
{
    __shared__ float e2s[NCODE];
    __shared__ int   s_tok[PPC];
    __shared__ float s_x2[PPC];
    __shared__ float sm_v1[PPC][2], sm_v2[PPC][2];
    __shared__ int   sm_ix[PPC][2];

    __nv_bfloat16* As = (__nv_bfloat16*)smem_dyn;
    const uint32_t As_u = smem_u32(smem_dyn);
    const uint32_t Bu[2] = { As_u + RA_BYTES, As_u + RA_BYTES + RB_BYTES };

    const int t      = threadIdx.x;
    const int lane   = t & 31;
    const int wid    = t >> 5;
    const int warp_m = wid & 3;
    const int warp_n = wid >> 2;

    #pragma unroll
    for (int i = 0; i < 4; i++) e2s[i * 256 + t] = g_e2[i * 256 + t];

    int cnt = g_fix1_cnt;
    if (cnt > FIX1_CAP) cnt = FIX1_CAP;

    uint32_t a_base[2];
    #pragma unroll
    for (int i = 0; i < 2; i++)
        a_base[i] = As_u + (warp_m * 32 + i * 16 + (lane & 15)) * (RASTRIDE * 2)
                  + (lane >> 4) * 16;
    const uint32_t b_row_off = (warp_n * 32 + (lane & 7)) * (RBSTRIDE * 2)
                             + ((lane >> 3) & 1) * 16;

    for (int tile = blockIdx.x; tile * PPC < cnt; tile += gridDim.x) {
        const int base = tile * PPC;
        const int rem  = min(PPC, cnt - base);
        __syncthreads();   // smem safe from previous tile

        // prefetch B chunk 0 (64 rows x 24 segs = 1536)
        #pragma unroll
        for (int i = 0; i < 6; i++) {
            int seg = i * 256 + t;
            int row = seg / 24, off = seg % 24;
            CP_ASYNC16(Bu[0] + row * (RBSTRIDE * 2) + off * 16,
                       (const char*)(g_Bpack192 + row * RKP) + off * 16);
        }
        CP_COMMIT();

        if (t < PPC) s_tok[t] = g_fix1[base + (t < rem ? t : 0)];
        __syncthreads();

        // gather A: slot t owns its token's 64 channels (strided HW)
        if (t < PPC) {
            const int p  = s_tok[t];
            const int b  = p >> 12;
            const int hw = p & 4095;
            float x2 = 0.f;
            #pragma unroll 8
            for (int c = 0; c < CH; c++) {
                float x = x_in[(b * CH + c) * HW + hw];
                x2 = fmaf(x, x, x2);
                __nv_bfloat16 hi = __float2bfloat16_rn(x);
                __nv_bfloat16 lo = __float2bfloat16_rn(x - __bfloat162float(hi));
                As[t * RASTRIDE + c]        = hi;   // A = [hi | hi | lo]
                As[t * RASTRIDE + 64 + c]   = hi;
                As[t * RASTRIDE + 128 + c]  = lo;
            }
            s_x2[t] = x2;
        }
        __syncthreads();

        float minv[4], min2[4];
        int   mini[4];
        #pragma unroll
        for (int s = 0; s < 4; s++) { minv[s] = 3.4e38f; min2[s] = 3.4e38f; mini[s] = 0; }

        for (int chunk = 0; chunk < NCHK; chunk++) {
            const int buf = chunk & 1;
            if (chunk + 1 < NCHK) {
                #pragma unroll
                for (int i = 0; i < 6; i++) {
                    int seg = i * 256 + t;
                    int row = seg / 24, off = seg % 24;
                    CP_ASYNC16(Bu[buf ^ 1] + row * (RBSTRIDE * 2) + off * 16,
                               (const char*)(g_Bpack192 + ((chunk + 1) * BROWS + row) * RKP) + off * 16);
                }
                CP_COMMIT();
                CP_WAIT1();
            } else {
                CP_WAIT0();
            }
            __syncthreads();

            float acc[2][4][4];
            #pragma unroll
            for (int i = 0; i < 2; i++)
                #pragma unroll
                for (int j = 0; j < 4; j++)
                    #pragma unroll
                    for (int r = 0; r < 4; r++) acc[i][j][r] = 0.f;

            #pragma unroll
            for (int kk = 0; kk < RKSTEPS; kk++) {
                uint32_t af[2][4], bf[4][2];
                #pragma unroll
                for (int i = 0; i < 2; i++) ldsm_x4(af[i], a_base[i] + kk * 32);
                #pragma unroll
                for (int j = 0; j < 4; j++)
                    ldsm_x2(bf[j], Bu[buf] + b_row_off + j * 8 * (RBSTRIDE * 2) + kk * 32);
                #pragma unroll
                for (int i = 0; i < 2; i++)
                    #pragma unroll
                    for (int j = 0; j < 4; j++)
                        mma_bf16(acc[i][j], af[i], bf[j]);
            }

            #pragma unroll
            for (int j = 0; j < 4; j++) {
                const int cb = chunk * BROWS + warp_n * 32 + j * 8 + (lane & 3) * 2;
                const float e20 = e2s[cb], e21 = e2s[cb + 1];
                #pragma unroll
                for (int i = 0; i < 2; i++) {
                    #pragma unroll
                    for (int h = 0; h < 2; h++) {
                        const int sl = i * 2 + h;
                        float s0 = fmaf(-2.f, acc[i][j][h * 2], e20);
                        float s1 = fmaf(-2.f, acc[i][j][h * 2 + 1], e21);
                        if (s0 < minv[sl]) { min2[sl] = minv[sl]; minv[sl] = s0; mini[sl] = cb; }
                        else if (s0 < min2[sl]) min2[sl] = s0;
                        if (s1 < minv[sl]) { min2[sl] = minv[sl]; minv[sl] = s1; mini[sl] = cb + 1; }
                        else if (s1 < min2[sl]) min2[sl] = s1;
                    }
                }
            }
            __syncthreads();
        }

        #pragma unroll
        for (int off = 1; off <= 2; off <<= 1) {
            #pragma unroll
            for (int s = 0; s < 4; s++) {
                float ov = __shfl_xor_sync(0xffffffffu, minv[s], off);
                int   oi = __shfl_xor_sync(0xffffffffu, mini[s], off);
                float o2 = __shfl_xor_sync(0xffffffffu, min2[s], off);
                float hi = fmaxf(minv[s], ov);
                min2[s] = fminf(fminf(min2[s], o2), hi);
                if (ov < minv[s] || (ov == minv[s] && oi < mini[s])) {
                    minv[s] = ov; mini[s] = oi;
                }
            }
        }
        if ((lane & 3) == 0) {
            #pragma unroll
            for (int s = 0; s < 4; s++) {
                int p = warp_m * 32 + (s >> 1) * 16 + (lane >> 2) + (s & 1) * 8;
                sm_v1[p][warp_n] = minv[s];
                sm_v2[p][warp_n] = min2[s];
                sm_ix[p][warp_n] = mini[s];
            }
        }
        __syncthreads();

        if (t < rem) {
            float v1 = sm_v1[t][0], v2 = sm_v2[t][0];
            int   ix = sm_ix[t][0];
            float w1 = sm_v1[t][1], w2 = sm_v2[t][1];
            int   wx = sm_ix[t][1];
            float hi = fmaxf(v1, w1);
            float m2 = fminf(fminf(v2, w2), hi);
            if (w1 < v1 || (w1 == v1 && wx < ix)) { v1 = w1; ix = wx; }

            const int p = s_tok[t];
            if (m2 - v1 < MARGIN2) {      // still ambiguous -> fp64 tier
                int slot = atomicAdd(&g_fix2_cnt, 1);
                if (slot < FIX2_CAP) g_fix2[slot] = p;
            }
            const int oldi = (int)out_idx[p];
            if (ix != oldi) {
                const int b  = p >> 12;
                const int hw = p & 4095;
                out_idx[p] = (float)ix;
                atomicAdd(&g_counts[oldi], -1);
                atomicAdd(&g_counts[ix],    1);
                float snew = v1 + s_x2[t];
                long long dq = llrint((double)snew * 1048576.0)
                             - llrint((double)g_scur[p] * 1048576.0);
                atomicAdd(&g_loss_sum, (unsigned long long)dq);
                g_scur[p] = snew;
                #pragma unroll 8
                for (int c = 0; c < CH; c++)
                    out_xq[(b * CH + c) * HW + hw] = emb[ix * CH + c];
            }
        }
    }
}

// ---------------------------------------------------------------------------
// Tier 3: warp-per-token exact fp64 argmin on the ~few-hundred survivors
// ---------------------------------------------------------------------------
__global__ __launch_bounds__(256) void vq_fixup64(
        const float* __restrict__ x_in,
        const float* __restrict__ emb,
        float* __restrict__ out_xq,
        float* __restrict__ out_idx)
{
    __shared__ double xw[8][CH];

    const int t    = threadIdx.x;
    const int lane = t & 31;
    const int wid  = t >> 5;
    int nfix = g_fix2_cnt;
    if (nfix > FIX2_CAP) nfix = FIX2_CAP;

    for (int f = blockIdx.x * 8 + wid; f < nfix; f += FIX2_WARPS) {
        const int p  = g_fix2[f];
        const int b  = p >> 12;
        const int hw = p & 4095;

        xw[wid][lane]      = (double)x_in[(b * CH + lane) * HW + hw];
        xw[wid][lane + 32] = (double)x_in[(b * CH + lane + 32) * HW + hw];
        __syncwarp();

        double bm = 1e300; int bi = 0;
        const int cbase = lane * 32;
        #pragma unroll 1
        for (int g = 0; g < 8; g++) {
            const float* e0 = emb + (cbase + g * 4 + 0) * CH;
            const float* e1 = emb + (cbase + g * 4 + 1) * CH;
            const float* e2 = emb + (cbase + g * 4 + 2) * CH;
            const float* e3 = emb + (cbase + g * 4 + 3) * CH;
            double a0 = 0, a1 = 0, a2 = 0, a3 = 0;
            #pragma unroll 8
            for (int k = 0; k < CH; k++) {
                double xv = xw[wid][k];
                double d0 = xv - (double)e0[k]; a0 = fma(d0, d0, a0);
                double d1 = xv - (double)e1[k]; a1 = fma(d1, d1, a1);
                double d2 = xv - (double)e2[k]; a2 = fma(d2, d2, a2);
                double d3 = xv - (double)e3[k]; a3 = fma(d3, d3, a3);
            }
            if (a0 < bm) { bm = a0; bi = cbase + g * 4 + 0; }
            if (a1 < bm) { bm = a1; bi = cbase + g * 4 + 1; }
            if (a2 < bm) { bm = a2; bi = cbase + g * 4 + 2; }
            if (a3 < bm) { bm = a3; bi = cbase + g * 4 + 3; }
        }
        #pragma unroll
        for (int off = 16; off >= 1; off >>= 1) {
            double ov = __shfl_xor_sync(0xffffffffu, bm, off);
            int    oi = __shfl_xor_sync(0xffffffffu, bi, off);
            if (ov < bm || (ov == bm && oi < bi)) { bm = ov; bi = oi; }
        }
        const int    newi = __shfl_sync(0xffffffffu, bi, 0);
        const double newd = __shfl_sync(0xffffffffu, bm, 0);
        const int    oldi = (int)out_idx[p];

        if (newi != oldi) {
            if (lane == 0) {
                atomicAdd(&g_counts[oldi], -1);
                atomicAdd(&g_counts[newi],  1);
                long long dq = llrint(newd * 1048576.0)
                             - llrint((double)g_scur[p] * 1048576.0);
                atomicAdd(&g_loss_sum, (unsigned long long)dq);
                out_idx[p] = (float)newi;
            }
            out_xq[(b * CH + lane) * HW + hw]      = emb[newi * CH + lane];
            out_xq[(b * CH + lane + 32) * HW + hw] = emb[newi * CH + lane + 32];
        }
        __syncwarp();
    }
}

// ---------------------------------------------------------------------------
// Epilogue: vq_loss + perplexity
// ---------------------------------------------------------------------------
__global__ void vq_final(float* __restrict__ out_tail) {
    __shared__ float red[256];
    int t = threadIdx.x;
    float s = 0.f;
    for (int c = t; c < NCODE; c += 256) {
        float p = (float)g_counts[c] * (1.0f / (float)NPIX);
        s += p * logf(p + 1e-10f);
    }
    red[t] = s;
    __syncthreads();
    #pragma unroll
    for (int off = 128; off > 0; off >>= 1) {
        if (t < off) red[t] += red[t + off];
        __syncthreads();
    }
    if (t == 0) {
        double loss_sum = (double)(long long)g_loss_sum / 1048576.0;
        float e_loss = (float)(loss_sum / (double)((long long)NPIX * CH));
        out_tail[0] = 0.25f * e_loss;   // BETA * e_loss
        out_tail[1] = expf(-red[0]);    // perplexity
    }
}

// ---------------------------------------------------------------------------
extern "C" void kernel_launch(void* const* d_in, const int* in_sizes, int n_in,
                              void* d_out, int out_size) {
    const float* x_in = (const float*)d_in[0];
    const float* emb  = (const float*)d_in[1];
    float* out      = (float*)d_out;
    float* out_xq   = out;
    float* out_idx  = out + XQ_ELEMS;
    float* out_tail = out + XQ_ELEMS + IDX_ELEMS;

    cudaFuncSetAttribute(vq_main, cudaFuncAttributeMaxDynamicSharedMemorySize,
                         DYN_SMEM);
    cudaFuncSetAttribute(vq_refine, cudaFuncAttributeMaxDynamicSharedMemorySize,
                         RDYN_SMEM);

    vq_prep   <<<(NCODE + 255) / 256, 256>>>(emb);
    vq_pack   <<<(NCODE + 255) / 256, 256>>>(emb);
    vq_main   <<<NPIX / PPC, 256, DYN_SMEM>>>(x_in, emb, out_xq, out_idx);
    vq_refine <<<224, 256, RDYN_SMEM>>>(x_in, emb, out_xq, out_idx);
    vq_fixup64<<<128, 256>>>(x_in, emb, out_xq, out_idx);
    vq_final  <<<1, 256>>>(out_tail);
}

// round 10
// speedup vs baseline: 1.2933x; 1.0623x over previous
#include <cuda_runtime.h>
#include <cuda_fp16.h>
#include <cuda_bf16.h>
#include <cstdint>

// Problem constants (fixed shapes per reference setup_inputs)
#define BATCH    32
#define CH       64
#define HW       4096          // 64*64
#define NPIX     131072        // BATCH*HW
#define NCODE    1024
#define PPC      128           // pixels per tile (= GEMM M)
#define BROWS    64            // codes per N-chunk (= GEMM N)
#define NCHK     (NCODE / BROWS)  // 16
#define NTILES   (NPIX / PPC)  // 1024
#define GRID_MAIN 148          // persistent: 1 CTA/SM
// ---- tier 1: fp16 hi-only ----
#define KDIM     64
#define KSTEPS   (KDIM / 16)   // 4
#define ASTRIDE  72            // 144B rows: 144%128=16 -> ldsm conflict-free
#define BSTRIDE  72
#define MARGIN1  0.04f
#define FIX1_CAP 49152
// ---- tier 2: bf16 3-term (proven R6/R9) ----
#define RKP      192
#define RKSTEPS  (RKP / 16)    // 12
#define RASTRIDE 200
#define RBSTRIDE 200
#define MARGIN2  1e-3f
#define FIX2_CAP 8192
#define FIX2_WARPS (128 * 8)

#define XQ_ELEMS  (NPIX * CH)
#define IDX_ELEMS NPIX

#define A_BYTES   (PPC * ASTRIDE * 2)     // 18432
#define BFULL_BYTES (NCODE * BSTRIDE * 2) // 147456 (entire codebook, fp16)
#define DYN_SMEM  (A_BYTES + BFULL_BYTES) // 165888

#define RA_BYTES  (PPC * RASTRIDE * 2)    // 51200
#define RB_BYTES  (BROWS * RBSTRIDE * 2)  // 25600
#define RDYN_SMEM (RA_BYTES + 2 * RB_BYTES)

// Scratch (device globals — no allocation allowed)
__device__ float              g_e2[NCODE];
__device__ int                g_counts[NCODE];
__device__ unsigned long long g_loss_sum;
__device__ int                g_fix1_cnt;
__device__ int                g_fix1[FIX1_CAP];
__device__ int                g_fix2_cnt;
__device__ int                g_fix2[FIX2_CAP];
__device__ float              g_scur[NPIX];
__device__ __half             g_Bpack64[NCODE * BSTRIDE];
__device__ __nv_bfloat16      g_Bpack192[NCODE * RKP];

// ---------------------------------------------------------------------------
// SM80+-vintage PTX helpers (base sm_100 safe)
// ---------------------------------------------------------------------------
__device__ __forceinline__ uint32_t smem_u32(const void* p) {
    uint32_t a;
    asm("{ .reg .u64 t; cvta.to.shared.u64 t, %1; cvt.u32.u64 %0, t; }"
        : "=r"(a) : "l"(p));
    return a;
}
__device__ __forceinline__ void ldsm_x4(uint32_t* r, uint32_t addr) {
    asm volatile("ldmatrix.sync.aligned.m8n8.x4.shared.b16 {%0,%1,%2,%3}, [%4];"
                 : "=r"(r[0]), "=r"(r[1]), "=r"(r[2]), "=r"(r[3]) : "r"(addr));
}
__device__ __forceinline__ void ldsm_x2(uint32_t* r, uint32_t addr) {
    asm volatile("ldmatrix.sync.aligned.m8n8.x2.shared.b16 {%0,%1}, [%2];"
                 : "=r"(r[0]), "=r"(r[1]) : "r"(addr));
}
__device__ __forceinline__ void mma_f16(float* d, const uint32_t* a, const uint32_t* b) {
    asm volatile(
        "mma.sync.aligned.m16n8k16.row.col.f32.f16.f16.f32 "
        "{%0,%1,%2,%3}, {%4,%5,%6,%7}, {%8,%9}, {%0,%1,%2,%3};"
        : "+f"(d[0]), "+f"(d[1]), "+f"(d[2]), "+f"(d[3])
        : "r"(a[0]), "r"(a[1]), "r"(a[2]), "r"(a[3]), "r"(b[0]), "r"(b[1]));
}
__device__ __forceinline__ void mma_bf16(float* d, const uint32_t* a, const uint32_t* b) {
    asm volatile(
        "mma.sync.aligned.m16n8k16.row.col.f32.bf16.bf16.f32 "
        "{%0,%1,%2,%3}, {%4,%5,%6,%7}, {%8,%9}, {%0,%1,%2,%3};"
        : "+f"(d[0]), "+f"(d[1]), "+f"(d[2]), "+f"(d[3])
        : "r"(a[0]), "r"(a[1]), "r"(a[2]), "r"(a[3]), "r"(b[0]), "r"(b[1]));
}
#define CP_ASYNC16(dst, src) \
    asm volatile("cp.async.cg.shared.global [%0], [%1], 16;" :: "r"(dst), "l"(src))
#define CP_COMMIT() asm volatile("cp.async.commit_group;" ::: "memory")
#define CP_WAIT1()  asm volatile("cp.async.wait_group 1;" ::: "memory")
#define CP_WAIT0()  asm volatile("cp.async.wait_group 0;" ::: "memory")

// ---------------------------------------------------------------------------
__global__ void vq_prep(const float* __restrict__ emb) {
    int c = blockIdx.x * blockDim.x + threadIdx.x;
    if (c < NCODE) {
        const float* row = emb + c * CH;
        float s = 0.f;
        #pragma unroll
        for (int k = 0; k < CH; k++) s = fmaf(row[k], row[k], s);
        g_e2[c]     = s;
        g_counts[c] = 0;
    }
    if (c == 0) { g_loss_sum = 0ull; g_fix1_cnt = 0; g_fix2_cnt = 0; }
}

__global__ void vq_pack(const float* __restrict__ emb) {
    int c = blockIdx.x * blockDim.x + threadIdx.x;
    if (c >= NCODE) return;
    __half*        d64  = g_Bpack64  + c * BSTRIDE;
    __nv_bfloat16* d192 = g_Bpack192 + c * RKP;
    #pragma unroll
    for (int k = 0; k < CH; k++) {
        float x = emb[c * CH + k];
        d64[k] = __float2half_rn(x);
        __nv_bfloat16 hi = __float2bfloat16_rn(x);
        __nv_bfloat16 lo = __float2bfloat16_rn(x - __bfloat162float(hi));
        d192[k]       = hi;
        d192[64 + k]  = lo;
        d192[128 + k] = hi;
    }
    #pragma unroll
    for (int k = CH; k < BSTRIDE; k++) d64[k] = __ushort_as_half(0);
}

// ---------------------------------------------------------------------------
// Tier 1: persistent CTAs, full fp16 codebook RESIDENT in smem (147 KB),
// zero barriers / zero cp.async in the N-loop, branchless top-2 epilogue.
// ---------------------------------------------------------------------------
extern __shared__ char smem_dyn[];   // A[128][72] fp16 | Bfull[1024][72] fp16

__global__ __launch_bounds__(256, 1) void vq_main(
        const float* __restrict__ x_in,
        const float* __restrict__ emb,
        float* __restrict__ out_xq,
        float* __restrict__ out_idx)
{
    __shared__ float e2s[NCODE];
    __shared__ float x2s[PPC];
    __shared__ int   ridx[PPC];
    __shared__ float sm_v1[PPC][2], sm_v2[PPC][2];
    __shared__ int   sm_ix[PPC][2];
    __shared__ unsigned long long s_loss;

    __half* As = (__half*)smem_dyn;
    const uint32_t As_u = smem_u32(smem_dyn);
    const uint32_t Bf_u = As_u + A_BYTES;

    const int t      = threadIdx.x;
    const int lane   = t & 31;
    const int wid    = t >> 5;
    const int warp_m = wid & 3;
    const int warp_n = wid >> 2;

    // ---- load FULL codebook into smem once (9216 x 16B segs, 36/thread) ----
    #pragma unroll
    for (int i = 0; i < 36; i++) {
        int seg = i * 256 + t;           // 0..9215
        int row = seg / 9, off = seg % 9;
        CP_ASYNC16(Bf_u + row * (BSTRIDE * 2) + off * 16,
                   (const char*)(g_Bpack64 + row * BSTRIDE) + off * 16);
    }
    CP_COMMIT();
    #pragma unroll
    for (int i = 0; i < 4; i++) e2s[i * 256 + t] = g_e2[i * 256 + t];
    CP_WAIT0();

    // ldmatrix addresses (bytes)
    uint32_t a_base[2];
    #pragma unroll
    for (int i = 0; i < 2; i++)
        a_base[i] = As_u + (warp_m * 32 + i * 16 + (lane & 15)) * (ASTRIDE * 2)
                  + (lane >> 4) * 16;
    const uint32_t b_row_off = Bf_u + (warp_n * 32 + (lane & 7)) * (BSTRIDE * 2)
                             + ((lane >> 3) & 1) * 16;

    for (int tile = blockIdx.x; tile < NTILES; tile += GRID_MAIN) {
        const int b     = tile >> 5;
        const int hw    = (tile & 31) * PPC;
        const int pbase = tile * PPC;

        __syncthreads();                 // prior tile fully consumed
        if (t == 0) s_loss = 0ull;
        if (t < PPC) x2s[t] = 0.f;
        __syncthreads();                 // zeros visible

        // ---- A tile: gmem [c][p] fp32 -> smem [p][k] fp16 + x2 ----
        #pragma unroll
        for (int r = 0; r < 8; r++) {
            int e  = r * 256 + t;
            int c  = e >> 5;
            int p4 = (e & 31) * 4;
            float4 v = *(const float4*)(x_in + (b * CH + c) * HW + hw + p4);
            float xv[4] = {v.x, v.y, v.z, v.w};
            #pragma unroll
            for (int q = 0; q < 4; q++) {
                int p = p4 + q;
                float x = xv[q];
                As[p * ASTRIDE + c] = __float2half_rn(x);
                atomicAdd(&x2s[p], x * x);
            }
        }
        __syncthreads();                 // A + x2 ready

        float minv[4], min2[4];
        int   mini[4];
        #pragma unroll
        for (int s = 0; s < 4; s++) { minv[s] = 3.4e38f; min2[s] = 3.4e38f; mini[s] = 0; }

        // ---- N-loop over resident B: no barriers, no async waits ----
        #pragma unroll 1
        for (int chunk = 0; chunk < NCHK; chunk++) {
            const uint32_t bchunk = b_row_off + chunk * (BROWS * BSTRIDE * 2);

            float acc[2][4][4];
            #pragma unroll
            for (int i = 0; i < 2; i++)
                #pragma unroll
                for (int j = 0; j < 4; j++)
                    #pragma unroll
                    for (int r = 0; r < 4; r++) acc[i][j][r] = 0.f;

            #pragma unroll
            for (int kk = 0; kk < KSTEPS; kk++) {
                uint32_t af[2][4], bf[4][2];
                #pragma unroll
                for (int i = 0; i < 2; i++) ldsm_x4(af[i], a_base[i] + kk * 32);
                #pragma unroll
                for (int j = 0; j < 4; j++)
                    ldsm_x2(bf[j], bchunk + j * 8 * (BSTRIDE * 2) + kk * 32);
                #pragma unroll
                for (int i = 0; i < 2; i++)
                    #pragma unroll
                    for (int j = 0; j < 4; j++)
                        mma_f16(acc[i][j], af[i], bf[j]);
            }

            // ---- branchless top-2 (codes ascend -> strict < keeps first) ----
            #pragma unroll
            for (int j = 0; j < 4; j++) {
                const int cb = chunk * BROWS + warp_n * 32 + j * 8 + (lane & 3) * 2;
                const float e20 = e2s[cb], e21 = e2s[cb + 1];
                #pragma unroll
                for (int i = 0; i < 2; i++) {
                    #pragma unroll
                    for (int h = 0; h < 2; h++) {
                        const int sl = i * 2 + h;
                        float s0 = fmaf(-2.f, acc[i][j][h * 2], e20);
                        float s1 = fmaf(-2.f, acc[i][j][h * 2 + 1], e21);
                        float o1 = minv[sl];
                        min2[sl] = fminf(min2[sl], fmaxf(s0, o1));
                        mini[sl] = (s0 < o1) ? cb : mini[sl];
                        minv[sl] = fminf(s0, o1);
                        o1 = minv[sl];
                        min2[sl] = fminf(min2[sl], fmaxf(s1, o1));
                        mini[sl] = (s1 < o1) ? (cb + 1) : mini[sl];
                        minv[sl] = fminf(s1, o1);
                    }
                }
            }
        }

        // ---- reduce across 4 lanes per row group ----
        #pragma unroll
        for (int off = 1; off <= 2; off <<= 1) {
            #pragma unroll
            for (int s = 0; s < 4; s++) {
                float ov = __shfl_xor_sync(0xffffffffu, minv[s], off);
                int   oi = __shfl_xor_sync(0xffffffffu, mini[s], off);
                float o2 = __shfl_xor_sync(0xffffffffu, min2[s], off);
                float hi = fmaxf(minv[s], ov);
                min2[s] = fminf(fminf(min2[s], o2), hi);
                if (ov < minv[s] || (ov == minv[s] && oi < mini[s])) {
                    minv[s] = ov; mini[s] = oi;
                }
            }
        }
        if ((lane & 3) == 0) {
            #pragma unroll
            for (int s = 0; s < 4; s++) {
                int p = warp_m * 32 + (s >> 1) * 16 + (lane >> 2) + (s & 1) * 8;
                sm_v1[p][warp_n] = minv[s];
                sm_v2[p][warp_n] = min2[s];
                sm_ix[p][warp_n] = mini[s];
            }
        }
        __syncthreads();

        // ---- per-pixel combine + outputs ----
        if (t < PPC) {
            float v1 = sm_v1[t][0], v2 = sm_v2[t][0];
            int   ix = sm_ix[t][0];
            float w1 = sm_v1[t][1], w2 = sm_v2[t][1];
            int   wx = sm_ix[t][1];
            float hi = fmaxf(v1, w1);
            float m2 = fminf(fminf(v2, w2), hi);
            if (w1 < v1 || (w1 == v1 && wx < ix)) { v1 = w1; ix = wx; }

            ridx[t] = ix;
            out_idx[pbase + t] = (float)ix;
            atomicAdd(&g_counts[ix], 1);
            float sc = v1 + x2s[t];
            g_scur[pbase + t] = sc;
            if (m2 - v1 < MARGIN1) {
                int slot = atomicAdd(&g_fix1_cnt, 1);
                if (slot < FIX1_CAP) g_fix1[slot] = pbase + t;
            }
            long long q = llrint((double)sc * 1048576.0);
            atomicAdd(&s_loss, (unsigned long long)q);
        }
        __syncthreads();                 // ridx + s_loss ready
        if (t == 0) atomicAdd(&g_loss_sum, s_loss);

        // ---- quantized output, channel-first, coalesced over pixels ----
        #pragma unroll
        for (int r = 0; r < 32; r++) {
            int e = r * 256 + t;
            int c = e >> 7;
            int p = e & 127;
            out_xq[(b * CH + c) * HW + hw + p] = emb[ridx[p] * CH + c];
        }
    }
}

// ---------------------------------------------------------------------------
// Tier 2: bf16 3-term K=192 GEMM on gathered flagged tokens (unchanged, 73us)
// ---------------------------------------------------------------------------
__global__ __launch_bounds__(256, 2) void vq_refine(
        const float* __restrict__ x_in,
        const float* __restrict__ emb,
        float* __restrict__ out_xq,
        float* __restrict__ out_idx)
{
    __shared__ float e2s[NCODE];
    __shared__ int   s_tok[PPC];
    __shared__ float s_x2[PPC];
    __shared__ float sm_v1[PPC][2], sm_v2[PPC][2];
    __shared__ int   sm_ix[PPC][2];

    __nv_bfloat16* As = (__nv_bfloat16*)smem_dyn;
    const uint32_t As_u = smem_u32(smem_dyn);
    const uint32_t Bu[2] = { As_u + RA_BYTES, As_u + RA_BYTES + RB_BYTES };

    const int t      = threadIdx.x;
    const int lane   = t & 31;
    const int wid    = t >> 5;
    const int warp_m = wid & 3;
    const int warp_n = wid >> 2;

    #pragma unroll
    for (int i = 0; i < 4; i++) e2s[i * 256 + t] = g_e2[i * 256 + t];

    int cnt = g_fix1_cnt;
    if (cnt > FIX1_CAP) cnt = FIX1_CAP;

    uint32_t a_base[2];
    #pragma unroll
    for (int i = 0; i < 2; i++)
        a_base[i] = As_u + (warp_m * 32 + i * 16 + (lane & 15)) * (RASTRIDE * 2)
                  + (lane >> 4) * 16;
    const uint32_t b_row_off = (warp_n * 32 + (lane & 7)) * (RBSTRIDE * 2)
                             + ((lane >> 3) & 1) * 16;

    for (int tile = blockIdx.x; tile * PPC < cnt; tile += gridDim.x) {
        const int base = tile * PPC;
        const int rem  = min(PPC, cnt - base);
        __syncthreads();

        #pragma unroll
        for (int i = 0; i < 6; i++) {
            int seg = i * 256 + t;
            int row = seg / 24, off = seg % 24;
            CP_ASYNC16(Bu[0] + row * (RBSTRIDE * 2) + off * 16,
                       (const char*)(g_Bpack192 + row * RKP) + off * 16);
        }
        CP_COMMIT();

        if (t < PPC) s_tok[t] = g_fix1[base + (t < rem ? t : 0)];
        __syncthreads();

        if (t < PPC) {
            const int p  = s_tok[t];
            const int b  = p >> 12;
            const int hw = p & 4095;
            float x2 = 0.f;
            #pragma unroll 8
            for (int c = 0; c < CH; c++) {
                float x = x_in[(b * CH + c) * HW + hw];
                x2 = fmaf(x, x, x2);
                __nv_bfloat16 hi = __float2bfloat16_rn(x);
                __nv_bfloat16 lo = __float2bfloat16_rn(x - __bfloat162float(hi));
                As[t * RASTRIDE + c]        = hi;
                As[t * RASTRIDE + 64 + c]   = hi;
                As[t * RASTRIDE + 128 + c]  = lo;
            }
            s_x2[t] = x2;
        }
        __syncthreads();

        float minv[4], min2[4];
        int   mini[4];
        #pragma unroll
        for (int s = 0; s < 4; s++) { minv[s] = 3.4e38f; min2[s] = 3.4e38f; mini[s] = 0; }

        for (int chunk = 0; chunk < NCHK; chunk++) {
            const int buf = chunk & 1;
            if (chunk + 1 < NCHK) {
                #pragma unroll
                for (int i = 0; i < 6; i++) {
                    int seg = i * 256 + t;
                    int row = seg / 24, off = seg % 24;
                    CP_ASYNC16(Bu[buf ^ 1] + row * (RBSTRIDE * 2) + off * 16,
                               (const char*)(g_Bpack192 + ((chunk + 1) * BROWS + row) * RKP) + off * 16);
                }
                CP_COMMIT();
                CP_WAIT1();
            } else {
                CP_WAIT0();
            }
            __syncthreads();

            float acc[2][4][4];
            #pragma unroll
            for (int i = 0; i < 2; i++)
                #pragma unroll
                for (int j = 0; j < 4; j++)
                    #pragma unroll
                    for (int r = 0; r < 4; r++) acc[i][j][r] = 0.f;

            #pragma unroll
            for (int kk = 0; kk < RKSTEPS; kk++) {
                uint32_t af[2][4], bf[4][2];
                #pragma unroll
                for (int i = 0; i < 2; i++) ldsm_x4(af[i], a_base[i] + kk * 32);
                #pragma unroll
                for (int j = 0; j < 4; j++)
                    ldsm_x2(bf[j], Bu[buf] + b_row_off + j * 8 * (RBSTRIDE * 2) + kk * 32);
                #pragma unroll
                for (int i = 0; i < 2; i++)
                    #pragma unroll
                    for (int j = 0; j < 4; j++)
                        mma_bf16(acc[i][j], af[i], bf[j]);
            }

            #pragma unroll
            for (int j = 0; j < 4; j++) {
                const int cb = chunk * BROWS + warp_n * 32 + j * 8 + (lane & 3) * 2;
                const float e20 = e2s[cb], e21 = e2s[cb + 1];
                #pragma unroll
                for (int i = 0; i < 2; i++) {
                    #pragma unroll
                    for (int h = 0; h < 2; h++) {
                        const int sl = i * 2 + h;
                        float s0 = fmaf(-2.f, acc[i][j][h * 2], e20);
                        float s1 = fmaf(-2.f, acc[i][j][h * 2 + 1], e21);
                        float o1 = minv[sl];
                        min2[sl] = fminf(min2[sl], fmaxf(s0, o1));
                        mini[sl] = (s0 < o1) ? cb : mini[sl];
                        minv[sl] = fminf(s0, o1);
                        o1 = minv[sl];
                        min2[sl] = fminf(min2[sl], fmaxf(s1, o1));
                        mini[sl] = (s1 < o1) ? (cb + 1) : mini[sl];
                        minv[sl] = fminf(s1, o1);
                    }
                }
            }
            __syncthreads();
        }

        #pragma unroll
        for (int off = 1; off <= 2; off <<= 1) {
            #pragma unroll
            for (int s = 0; s < 4; s++) {
                float ov = __shfl_xor_sync(0xffffffffu, minv[s], off);
                int   oi = __shfl_xor_sync(0xffffffffu, mini[s], off);
                float o2 = __shfl_xor_sync(0xffffffffu, min2[s], off);
                float hi = fmaxf(minv[s], ov);
                min2[s] = fminf(fminf(min2[s], o2), hi);
                if (ov < minv[s] || (ov == minv[s] && oi < mini[s])) {
                    minv[s] = ov; mini[s] = oi;
                }
            }
        }
        if ((lane & 3) == 0) {
            #pragma unroll
            for (int s = 0; s < 4; s++) {
                int p = warp_m * 32 + (s >> 1) * 16 + (lane >> 2) + (s & 1) * 8;
                sm_v1[p][warp_n] = minv[s];
                sm_v2[p][warp_n] = min2[s];
                sm_ix[p][warp_n] = mini[s];
            }
        }
        __syncthreads();

        if (t < rem) {
            float v1 = sm_v1[t][0], v2 = sm_v2[t][0];
            int   ix = sm_ix[t][0];
            float w1 = sm_v1[t][1], w2 = sm_v2[t][1];
            int   wx = sm_ix[t][1];
            float hi = fmaxf(v1, w1);
            float m2 = fminf(fminf(v2, w2), hi);
            if (w1 < v1 || (w1 == v1 && wx < ix)) { v1 = w1; ix = wx; }

            const int p = s_tok[t];
            if (m2 - v1 < MARGIN2) {
                int slot = atomicAdd(&g_fix2_cnt, 1);
                if (slot < FIX2_CAP) g_fix2[slot] = p;
            }
            const int oldi = (int)out_idx[p];
            if (ix != oldi) {
                const int b  = p >> 12;
                const int hw = p & 4095;
                out_idx[p] = (float)ix;
                atomicAdd(&g_counts[oldi], -1);
                atomicAdd(&g_counts[ix],    1);
                float snew = v1 + s_x2[t];
                long long dq = llrint((double)snew * 1048576.0)
                             - llrint((double)g_scur[p] * 1048576.0);
                atomicAdd(&g_loss_sum, (unsigned long long)dq);
                g_scur[p] = snew;
                #pragma unroll 8
                for (int c = 0; c < CH; c++)
                    out_xq[(b * CH + c) * HW + hw] = emb[ix * CH + c];
            }
        }
    }
}

// ---------------------------------------------------------------------------
// Tier 3: warp-per-token exact fp64 argmin (unchanged)
// ---------------------------------------------------------------------------
__global__ __launch_bounds__(256) void vq_fixup64(
        const float* __restrict__ x_in,
        const float* __restrict__ emb,
        float* __restrict__ out_xq,
        float* __restrict__ out_idx)
{
    __shared__ double xw[8][CH];

    const int t    = threadIdx.x;
    const int lane = t & 31;
    const int wid  = t >> 5;
    int nfix = g_fix2_cnt;
    if (nfix > FIX2_CAP) nfix = FIX2_CAP;

    for (int f = blockIdx.x * 8 + wid; f < nfix; f += FIX2_WARPS) {
        const int p  = g_fix2[f];
        const int b  = p >> 12;
        const int hw = p & 4095;

        xw[wid][lane]      = (double)x_in[(b * CH + lane) * HW + hw];
        xw[wid][lane + 32] = (double)x_in[(b * CH + lane + 32) * HW + hw];
        __syncwarp();

        double bm = 1e300; int bi = 0;
        const int cbase = lane * 32;
        #pragma unroll 1
        for (int g = 0; g < 8; g++) {
            const float* e0 = emb + (cbase + g * 4 + 0) * CH;
            const float* e1 = emb + (cbase + g * 4 + 1) * CH;
            const float* e2 = emb + (cbase + g * 4 + 2) * CH;
            const float* e3 = emb + (cbase + g * 4 + 3) * CH;
            double a0 = 0, a1 = 0, a2 = 0, a3 = 0;
            #pragma unroll 8
            for (int k = 0; k < CH; k++) {
                double xv = xw[wid][k];
                double d0 = xv - (double)e0[k]; a0 = fma(d0, d0, a0);
                double d1 = xv - (double)e1[k]; a1 = fma(d1, d1, a1);
                double d2 = xv - (double)e2[k]; a2 = fma(d2, d2, a2);
                double d3 = xv - (double)e3[k]; a3 = fma(d3, d3, a3);
            }
            if (a0 < bm) { bm = a0; bi = cbase + g * 4 + 0; }
            if (a1 < bm) { bm = a1; bi = cbase + g * 4 + 1; }
            if (a2 < bm) { bm = a2; bi = cbase + g * 4 + 2; }
            if (a3 < bm) { bm = a3; bi = cbase + g * 4 + 3; }
        }
        #pragma unroll
        for (int off = 16; off >= 1; off >>= 1) {
            double ov = __shfl_xor_sync(0xffffffffu, bm, off);
            int    oi = __shfl_xor_sync(0xffffffffu, bi, off);
            if (ov < bm || (ov == bm && oi < bi)) { bm = ov; bi = oi; }
        }
        const int    newi = __shfl_sync(0xffffffffu, bi, 0);
        const double newd = __shfl_sync(0xffffffffu, bm, 0);
        const int    oldi = (int)out_idx[p];

        if (newi != oldi) {
            if (lane == 0) {
                atomicAdd(&g_counts[oldi], -1);
                atomicAdd(&g_counts[newi],  1);
                long long dq = llrint(newd * 1048576.0)
                             - llrint((double)g_scur[p] * 1048576.0);
                atomicAdd(&g_loss_sum, (unsigned long long)dq);
                out_idx[p] = (float)newi;
            }
            out_xq[(b * CH + lane) * HW + hw]      = emb[newi * CH + lane];
            out_xq[(b * CH + lane + 32) * HW + hw] = emb[newi * CH + lane + 32];
        }
        __syncwarp();
    }
}

// ---------------------------------------------------------------------------
__global__ void vq_final(float* __restrict__ out_tail) {
    __shared__ float red[256];
    int t = threadIdx.x;
    float s = 0.f;
    for (int c = t; c < NCODE; c += 256) {
        float p = (float)g_counts[c] * (1.0f / (float)NPIX);
        s += p * logf(p + 1e-10f);
    }
    red[t] = s;
    __syncthreads();
    #pragma unroll
    for (int off = 128; off > 0; off >>= 1) {
        if (t < off) red[t] += red[t + off];
        __syncthreads();
    }
    if (t == 0) {
        double loss_sum = (double)(long long)g_loss_sum / 1048576.0;
        float e_loss = (float)(loss_sum / (double)((long long)NPIX * CH));
        out_tail[0] = 0.25f * e_loss;   // BETA * e_loss
        out_tail[1] = expf(-red[0]);    // perplexity
    }
}

// ---------------------------------------------------------------------------
extern "C" void kernel_launch(void* const* d_in, const int* in_sizes, int n_in,
                              void* d_out, int out_size) {
    const float* x_in = (const float*)d_in[0];
    const float* emb  = (const float*)d_in[1];
    float* out      = (float*)d_out;
    float* out_xq   = out;
    float* out_idx  = out + XQ_ELEMS;
    float* out_tail = out + XQ_ELEMS + IDX_ELEMS;

    cudaFuncSetAttribute(vq_main, cudaFuncAttributeMaxDynamicSharedMemorySize,
                         DYN_SMEM);
    cudaFuncSetAttribute(vq_refine, cudaFuncAttributeMaxDynamicSharedMemorySize,
                         RDYN_SMEM);

    vq_prep   <<<(NCODE + 255) / 256, 256>>>(emb);
    vq_pack   <<<(NCODE + 255) / 256, 256>>>(emb);
    vq_main   <<<GRID_MAIN, 256, DYN_SMEM>>>(x_in, emb, out_xq, out_idx);
    vq_refine <<<224, 256, RDYN_SMEM>>>(x_in, emb, out_xq, out_idx);
    vq_fixup64<<<128, 256>>>(x_in, emb, out_xq, out_idx);
    vq_final  <<<1, 256>>>(out_tail);
}